// round 4
// baseline (speedup 1.0000x reference)
#include <cuda_runtime.h>

#define IH 384
#define IW 384
#define HO 382
#define WO 382
#define NB 8
#define HALO 6
#define TH 22          // rows [ho0-6, ho0+15]
#define TW 46          // cols [wo0-6, wo0+39]
#define TILE_CH (TH * TW)   // 1012

typedef unsigned long long u64;

__device__ __forceinline__ u64 fma2(u64 a, u64 b, u64 c) {
    u64 d; asm("fma.rn.f32x2 %0, %1, %2, %3;" : "=l"(d) : "l"(a), "l"(b), "l"(c)); return d;
}
__device__ __forceinline__ u64 pack2(float lo, float hi) {
    u64 r; asm("mov.b64 %0, {%1, %2};" : "=l"(r) : "f"(lo), "f"(hi)); return r;
}
__device__ __forceinline__ void unpack2(u64 v, float& lo, float& hi) {
    asm("mov.b64 {%0, %1}, %2;" : "=f"(lo), "=f"(hi) : "l"(v));
}

__global__ __launch_bounds__(128, 5)
void deform_fused4(const float* __restrict__ x,
                   const float* __restrict__ w1,
                   const float* __restrict__ b1,
                   const float* __restrict__ w2,
                   const float* __restrict__ b2,
                   float* __restrict__ out)
{
    __shared__ float2 s_t01[TILE_CH];                 // (ch0, ch1), zero-filled outside image
    __shared__ float  s_t2[TILE_CH];                  // ch2
    __shared__ __align__(16) ulonglong2 s_w1q[9 * 27]; // per (kk,j): ((wdy,wdy),(wdx,wdx))
    __shared__ u64 s_b1d[9], s_b1x[9];                // dup biases
    __shared__ u64 s_w2d[81];                         // dup(w2[o][c][kk])
    __shared__ u64 s_b2d[3];

    const int tid = threadIdx.y * 32 + threadIdx.x;

    // ---- weights to shared ----
    for (int i = tid; i < 9 * 27; i += 128) {
        int kk = i / 27, j = i - kk * 27;
        float dyw = w1[(2 * kk) * 27 + j];
        float dxw = w1[(2 * kk + 1) * 27 + j];
        ulonglong2 q; q.x = pack2(dyw, dyw); q.y = pack2(dxw, dxw);
        s_w1q[i] = q;
    }
    for (int i = tid; i < 9; i += 128) {
        s_b1d[i] = pack2(b1[2 * i],     b1[2 * i]);
        s_b1x[i] = pack2(b1[2 * i + 1], b1[2 * i + 1]);
    }
    if (tid < 81) { float v = w2[tid]; s_w2d[tid] = pack2(v, v); }
    if (tid < 3)  { float v = b2[tid]; s_b2d[tid] = pack2(v, v); }

    const int wo0 = blockIdx.x * 32;
    const int ho0 = blockIdx.y * 8;
    const int b   = blockIdx.z;
    const float* __restrict__ xb = x + (size_t)b * 3 * IH * IW;

    const int rowBase = ho0 - HALO;
    const int colBase = wo0 - HALO;

    // ---- input tile to shared (zero-filled outside image) ----
    for (int i = tid; i < TILE_CH; i += 128) {
        int r   = i / TW;
        int col = i - r * TW;
        int gy = rowBase + r;
        int gx = colBase + col;
        float v0 = 0.f, v1 = 0.f, v2 = 0.f;
        if ((unsigned)gy < IH && (unsigned)gx < IW) {
            const float* p = xb + (size_t)gy * IW + gx;
            v0 = __ldg(p);
            v1 = __ldg(p + IH * IW);
            v2 = __ldg(p + 2 * IH * IW);
        }
        s_t01[i] = make_float2(v0, v1);
        s_t2[i]  = v2;
    }
    __syncthreads();

    const int wo  = wo0 + threadIdx.x;
    const int hoA = ho0 + 2 * threadIdx.y;       // pixel pair rows hoA, hoA+1
    const int ltx = threadIdx.x + HALO;
    const int lty = 2 * threadIdx.y + HALO;

    // ---- window as vertical pixel-pairs: wpair[c*9 + r*3 + kw] = (row lty+r, row lty+r+1) ----
    float rowv[4][3][3];   // [r][kw][c]
#pragma unroll
    for (int r = 0; r < 4; r++)
#pragma unroll
        for (int kw = 0; kw < 3; kw++) {
            int idx = (lty + r) * TW + (ltx + kw);
            float2 v01 = s_t01[idx];
            rowv[r][kw][0] = v01.x;
            rowv[r][kw][1] = v01.y;
            rowv[r][kw][2] = s_t2[idx];
        }
    u64 wpair[27];
#pragma unroll
    for (int c = 0; c < 3; c++)
#pragma unroll
        for (int r = 0; r < 3; r++)
#pragma unroll
            for (int kw = 0; kw < 3; kw++)
                wpair[c * 9 + r * 3 + kw] = pack2(rowv[r][kw][c], rowv[r + 1][kw][c]);

    u64 accp[3];
#pragma unroll
    for (int o = 0; o < 3; o++) accp[o] = s_b2d[o];

#pragma unroll 1
    for (int kk = 0; kk < 9; kk++) {
        // ---- offset conv: ady=(dy_p0,dy_p1), adx=(dx_p0,dx_p1) ----
        u64 ady = s_b1d[kk];
        u64 adx = s_b1x[kk];
        const ulonglong2* __restrict__ wq = &s_w1q[kk * 27];
#pragma unroll
        for (int j = 0; j < 27; j++) {
            ulonglong2 w = wq[j];
            u64 wp = wpair[j];
            ady = fma2(wp, w.x, ady);
            adx = fma2(wp, w.y, adx);
        }

        const int kh = kk / 3;
        const int kw = kk - 3 * kh;

        float dy0, dy1, dx0, dx1;
        unpack2(ady, dy0, dy1);
        unpack2(adx, dx0, dx1);

        float vch[2][3];
#pragma unroll
        for (int p = 0; p < 2; p++) {
            float py = (float)(hoA + p + kh) + (p ? dy1 : dy0);
            float px = (float)(wo + kw)      + (p ? dx1 : dx0);
            int y0 = __float2int_rd(py);
            int x0 = __float2int_rd(px);
            float wy = py - (float)y0;
            float wx = px - (float)x0;
            int ly0 = y0 - rowBase;
            int lx0 = x0 - colBase;

            float c00 = (1.f - wy) * (1.f - wx);
            float c01 = (1.f - wy) * wx;
            float c10 = wy * (1.f - wx);
            float c11 = wy * wx;

            if ((unsigned)ly0 <= TH - 2 && (unsigned)lx0 <= TW - 2) {
                // fast path: zero-filled tile makes reference validity masks redundant
                int t = ly0 * TW + lx0;
                float2 a01 = s_t01[t];
                float2 b01 = s_t01[t + 1];
                float2 g01 = s_t01[t + TW];
                float2 h01 = s_t01[t + TW + 1];
                float a2 = s_t2[t],      b2v = s_t2[t + 1];
                float g2 = s_t2[t + TW], h2  = s_t2[t + TW + 1];

                vch[p][0] = fmaf(c11, h01.x, fmaf(c10, g01.x, fmaf(c01, b01.x, c00 * a01.x)));
                vch[p][1] = fmaf(c11, h01.y, fmaf(c10, g01.y, fmaf(c01, b01.y, c00 * a01.y)));
                vch[p][2] = fmaf(c11, h2,    fmaf(c10, g2,    fmaf(c01, b2v,   c00 * a2)));
            } else {
                // rare slow path: exact reference semantics (clamp + validity)
                bool vy0 = (y0 >= 0)  && (y0 <= IH - 1);
                bool vy1 = (y0 >= -1) && (y0 <= IH - 2);
                bool vx0 = (x0 >= 0)  && (x0 <= IW - 1);
                bool vx1 = (x0 >= -1) && (x0 <= IW - 2);
                float m00 = c00 * ((vy0 && vx0) ? 1.f : 0.f);
                float m01 = c01 * ((vy0 && vx1) ? 1.f : 0.f);
                float m10 = c10 * ((vy1 && vx0) ? 1.f : 0.f);
                float m11 = c11 * ((vy1 && vx1) ? 1.f : 0.f);
                int yc0 = min(max(y0, 0), IH - 1);
                int yc1 = min(max(y0 + 1, 0), IH - 1);
                int xc0 = min(max(x0, 0), IW - 1);
                int xc1 = min(max(x0 + 1, 0), IW - 1);
                int i00 = yc0 * IW + xc0;
                int i01 = yc0 * IW + xc1;
                int i10 = yc1 * IW + xc0;
                int i11 = yc1 * IW + xc1;
#pragma unroll
                for (int c = 0; c < 3; c++) {
                    const float* __restrict__ xc = xb + (size_t)c * IH * IW;
                    vch[p][c] = m00 * __ldg(xc + i00) + m01 * __ldg(xc + i01)
                              + m10 * __ldg(xc + i10) + m11 * __ldg(xc + i11);
                }
            }
        }

        // ---- accumulate both pixels: acc[o] += dup(w2[o][c][kk]) * (v_p0, v_p1) ----
#pragma unroll
        for (int c = 0; c < 3; c++) {
            u64 vp = pack2(vch[0][c], vch[1][c]);
            accp[0] = fma2(s_w2d[0 * 27 + c * 9 + kk], vp, accp[0]);
            accp[1] = fma2(s_w2d[1 * 27 + c * 9 + kk], vp, accp[1]);
            accp[2] = fma2(s_w2d[2 * 27 + c * 9 + kk], vp, accp[2]);
        }
    }

    // ---- store ----
    if (wo < WO) {
        const size_t plane = (size_t)HO * WO;
        const size_t base  = (size_t)b * 3 * plane + (size_t)hoA * WO + wo;
        float a0, a1;
#pragma unroll
        for (int o = 0; o < 3; o++) {
            unpack2(accp[o], a0, a1);
            if (hoA < HO)     out[base + o * plane]      = a0;
            if (hoA + 1 < HO) out[base + o * plane + WO] = a1;
        }
    }
}

extern "C" void kernel_launch(void* const* d_in, const int* in_sizes, int n_in,
                              void* d_out, int out_size)
{
    const float* x  = (const float*)d_in[0];
    const float* w1 = (const float*)d_in[1];
    const float* b1 = (const float*)d_in[2];
    const float* w2 = (const float*)d_in[3];
    const float* b2 = (const float*)d_in[4];
    float* out = (float*)d_out;

    cudaFuncSetAttribute(deform_fused4, cudaFuncAttributePreferredSharedMemoryCarveout, 100);

    dim3 block(32, 4, 1);
    dim3 grid((WO + 31) / 32, (HO + 7) / 8, NB);
    deform_fused4<<<grid, block>>>(x, w1, b1, w2, b2, out);
}

// round 5
// speedup vs baseline: 1.5056x; 1.5056x over previous
#include <cuda_runtime.h>

#define IH 384
#define IW 384
#define HO 382
#define WO 382
#define NB 8
#define HALO 6
#define TH 22          // rows [ho0-6, ho0+15]
#define TW 46          // cols [wo0-6, wo0+39]
#define TILE_CH (TH * TW)   // 1012

typedef unsigned long long u64;

__device__ __forceinline__ u64 fma2(u64 a, u64 b, u64 c) {
    u64 d;
    asm("fma.rn.f32x2 %0, %1, %2, %3;" : "=l"(d) : "l"(a), "l"(b), "l"(c));
    return d;
}
__device__ __forceinline__ u64 pack2(float lo, float hi) {
    u64 r;
    asm("mov.b64 %0, {%1, %2};" : "=l"(r) : "f"(lo), "f"(hi));
    return r;
}
__device__ __forceinline__ void unpack2(u64 v, float& lo, float& hi) {
    asm("mov.b64 {%0, %1}, %2;" : "=f"(lo), "=f"(hi) : "l"(v));
}

__global__ __launch_bounds__(128, 4)
void deform_fused5(const float* __restrict__ x,
                   const float* __restrict__ w1,
                   const float* __restrict__ b1,
                   const float* __restrict__ w2,
                   const float* __restrict__ b2,
                   float* __restrict__ out)
{
    __shared__ float s_tile[3 * TILE_CH];
    __shared__ __align__(16) u64 s_w1p[9 * 28];   // [kk][j] packed (wdy, wdx), stride 28 keeps 16B align
    __shared__ u64 s_b1p[9];
    __shared__ float s_w2[3 * 27];
    __shared__ float s_b2[3];

    const int tid = threadIdx.y * 32 + threadIdx.x;

    // ---- weights to shared ----
    for (int i = tid; i < 9 * 27; i += 128) {
        int kk = i / 27, j = i % 27;
        s_w1p[kk * 28 + j] = pack2(w1[(2 * kk) * 27 + j], w1[(2 * kk + 1) * 27 + j]);
    }
    for (int i = tid; i < 9; i += 128) {
        s_w1p[i * 28 + 27] = 0ull;                 // pad slot
        s_b1p[i] = pack2(b1[2 * i], b1[2 * i + 1]);
    }
    if (tid < 81) s_w2[tid] = w2[tid];
    if (tid < 3)  s_b2[tid] = b2[tid];

    const int wo0 = blockIdx.x * 32;
    const int ho0 = blockIdx.y * 8;
    const int b   = blockIdx.z;
    const float* __restrict__ xb = x + (size_t)b * 3 * IH * IW;

    const int rowBase = ho0 - HALO;
    const int colBase = wo0 - HALO;

    // ---- input tile to shared (zero-filled outside image) ----
    for (int i = tid; i < 3 * TILE_CH; i += 128) {
        int c  = i / TILE_CH;
        int rr = i - c * TILE_CH;
        int r  = rr / TW;
        int col = rr - r * TW;
        int gy = rowBase + r;
        int gx = colBase + col;
        float v = 0.f;
        if ((unsigned)gy < IH && (unsigned)gx < IW)
            v = __ldg(xb + ((size_t)c * IH + gy) * IW + gx);
        s_tile[i] = v;
    }
    __syncthreads();

    const int wo  = wo0 + threadIdx.x;       // may be >= WO for 2 lanes in edge blocks
    const int hoA = ho0 + 2 * threadIdx.y;   // pixel pair rows hoA, hoA+1
    const int ltx = threadIdx.x + HALO;
    const int lty = 2 * threadIdx.y + HALO;

    // ---- window (4 rows x 3 cols x 3 ch) duplicated-packed in registers ----
    u64 wr2[3][4][3];
#pragma unroll
    for (int c = 0; c < 3; c++)
#pragma unroll
        for (int r = 0; r < 4; r++)
#pragma unroll
            for (int kw = 0; kw < 3; kw++) {
                float v = s_tile[c * TILE_CH + (lty + r) * TW + (ltx + kw)];
                wr2[c][r][kw] = pack2(v, v);
            }

    float acc[2][3];
#pragma unroll
    for (int p = 0; p < 2; p++)
#pragma unroll
        for (int o = 0; o < 3; o++) acc[p][o] = s_b2[o];

#pragma unroll 1
    for (int kk = 0; kk < 9; kk++) {
        // ---- offset conv for this kk, both pixels, packed (dy,dx) ----
        u64 a0 = s_b1p[kk];
        u64 a1 = a0;
        const u64* __restrict__ wp = &s_w1p[kk * 28];
#pragma unroll
        for (int j = 0; j < 27; j++) {
            int c  = j / 9;
            int kh = (j / 3) % 3;
            int kw = j % 3;
            u64 w = wp[j];
            a0 = fma2(wr2[c][kh][kw],     w, a0);
            a1 = fma2(wr2[c][kh + 1][kw], w, a1);
        }

        const int kh = kk / 3;
        const int kw = kk - 3 * kh;

#pragma unroll
        for (int p = 0; p < 2; p++) {
            float dy, dx;
            unpack2(p ? a1 : a0, dy, dx);
            int ho = hoA + p;
            float py = (float)(ho + kh) + dy;
            float px = (float)(wo + kw) + dx;
            int y0 = __float2int_rd(py);
            int x0 = __float2int_rd(px);
            float wy = py - (float)y0;
            float wx = px - (float)x0;

            float c00 = (1.f - wy) * (1.f - wx);
            float c01 = (1.f - wy) * wx;
            float c10 = wy * (1.f - wx);
            float c11 = wy * wx;

            int ly0 = y0 - rowBase;
            int lx0 = x0 - colBase;

            if ((unsigned)ly0 <= TH - 2 && (unsigned)lx0 <= TW - 2) {
                // fast path: zero-filled tile makes the reference validity masks redundant
                int t = ly0 * TW + lx0;
#pragma unroll
                for (int c = 0; c < 3; c++) {
                    const float* __restrict__ tc = &s_tile[c * TILE_CH + t];
                    float v = c00 * tc[0];
                    v = fmaf(c01, tc[1], v);
                    v = fmaf(c10, tc[TW], v);
                    v = fmaf(c11, tc[TW + 1], v);
                    acc[p][0] = fmaf(v, s_w2[0 * 27 + c * 9 + kk], acc[p][0]);
                    acc[p][1] = fmaf(v, s_w2[1 * 27 + c * 9 + kk], acc[p][1]);
                    acc[p][2] = fmaf(v, s_w2[2 * 27 + c * 9 + kk], acc[p][2]);
                }
            } else {
                // rare slow path: clamped global loads (exact reference semantics)
                bool vy0 = (y0 >= 0)  && (y0 <= IH - 1);
                bool vy1 = (y0 >= -1) && (y0 <= IH - 2);
                bool vx0 = (x0 >= 0)  && (x0 <= IW - 1);
                bool vx1 = (x0 >= -1) && (x0 <= IW - 2);
                float m00 = c00 * ((vy0 && vx0) ? 1.f : 0.f);
                float m01 = c01 * ((vy0 && vx1) ? 1.f : 0.f);
                float m10 = c10 * ((vy1 && vx0) ? 1.f : 0.f);
                float m11 = c11 * ((vy1 && vx1) ? 1.f : 0.f);
                int yc0 = min(max(y0, 0), IH - 1);
                int yc1 = min(max(y0 + 1, 0), IH - 1);
                int xc0 = min(max(x0, 0), IW - 1);
                int xc1 = min(max(x0 + 1, 0), IW - 1);
                int i00 = yc0 * IW + xc0;
                int i01 = yc0 * IW + xc1;
                int i10 = yc1 * IW + xc0;
                int i11 = yc1 * IW + xc1;
#pragma unroll
                for (int c = 0; c < 3; c++) {
                    const float* __restrict__ xc = xb + (size_t)c * IH * IW;
                    float v = m00 * __ldg(xc + i00) + m01 * __ldg(xc + i01)
                            + m10 * __ldg(xc + i10) + m11 * __ldg(xc + i11);
                    acc[p][0] = fmaf(v, s_w2[0 * 27 + c * 9 + kk], acc[p][0]);
                    acc[p][1] = fmaf(v, s_w2[1 * 27 + c * 9 + kk], acc[p][1]);
                    acc[p][2] = fmaf(v, s_w2[2 * 27 + c * 9 + kk], acc[p][2]);
                }
            }
        }
    }

    // ---- store ----
    if (wo < WO) {
        const size_t plane = (size_t)HO * WO;
#pragma unroll
        for (int p = 0; p < 2; p++) {
            int ho = hoA + p;
            if (ho < HO) {
                size_t ob = (size_t)b * 3 * plane + (size_t)ho * WO + wo;
                out[ob]             = acc[p][0];
                out[ob + plane]     = acc[p][1];
                out[ob + 2 * plane] = acc[p][2];
            }
        }
    }
}

extern "C" void kernel_launch(void* const* d_in, const int* in_sizes, int n_in,
                              void* d_out, int out_size)
{
    const float* x  = (const float*)d_in[0];
    const float* w1 = (const float*)d_in[1];
    const float* b1 = (const float*)d_in[2];
    const float* w2 = (const float*)d_in[3];
    const float* b2 = (const float*)d_in[4];
    float* out = (float*)d_out;

    dim3 block(32, 4, 1);
    dim3 grid((WO + 31) / 32, (HO + 7) / 8, NB);
    deform_fused5<<<grid, block>>>(x, w1, b1, w2, b2, out);
}